// round 2
// baseline (speedup 1.0000x reference)
#include <cuda_runtime.h>

#define N_NODES 768
#define INP     256
#define H       4
#define FH      64
#define OUTD    256   // H*FH

// Scratch (no cudaMalloc allowed)
__device__ float g_Wx[N_NODES * OUTD];
__device__ float g_E[N_NODES * H];

// ---------------------------------------------------------------------------
// GEMM: Wx = x @ W^T   (M=768, K=256, Ncols=256)
// BM=32, BN=64, BK=32, 256 threads, 2x4 per-thread tile. Grid (4, 24) = 96 blocks.
// ---------------------------------------------------------------------------
__global__ __launch_bounds__(256) void gemm_kernel(const float* __restrict__ x,
                                                   const float* __restrict__ W) {
    __shared__ float As[32][36];   // As[k][m]
    __shared__ float Bs[32][68];   // Bs[k][n]
    const int tid = threadIdx.x;
    const int m0 = blockIdx.y * 32;
    const int n0 = blockIdx.x * 64;

    const int tx = tid % 16;   // n quad
    const int ty = tid / 16;   // m pair
    float acc[2][4] = {};

    for (int k0 = 0; k0 < INP; k0 += 32) {
        {   // load x tile: 32(m) x 32(k)
            const int r  = tid / 8;
            const int c4 = tid % 8;
            float4 v = *reinterpret_cast<const float4*>(&x[(m0 + r) * INP + k0 + c4 * 4]);
            As[c4 * 4 + 0][r] = v.x;
            As[c4 * 4 + 1][r] = v.y;
            As[c4 * 4 + 2][r] = v.z;
            As[c4 * 4 + 3][r] = v.w;
        }
        {   // load W tile: 64(n) x 32(k)
            const int r  = tid / 8;
            const int c4 = tid % 8;
            #pragma unroll
            for (int half = 0; half < 2; half++) {
                const int n = r + half * 32;
                float4 v = *reinterpret_cast<const float4*>(&W[(n0 + n) * INP + k0 + c4 * 4]);
                Bs[c4 * 4 + 0][n] = v.x;
                Bs[c4 * 4 + 1][n] = v.y;
                Bs[c4 * 4 + 2][n] = v.z;
                Bs[c4 * 4 + 3][n] = v.w;
            }
        }
        __syncthreads();
        #pragma unroll
        for (int k = 0; k < 32; k++) {
            float2 av = *reinterpret_cast<const float2*>(&As[k][ty * 2]);
            float4 bv = *reinterpret_cast<const float4*>(&Bs[k][tx * 4]);
            acc[0][0] += av.x * bv.x; acc[0][1] += av.x * bv.y;
            acc[0][2] += av.x * bv.z; acc[0][3] += av.x * bv.w;
            acc[1][0] += av.y * bv.x; acc[1][1] += av.y * bv.y;
            acc[1][2] += av.y * bv.z; acc[1][3] += av.y * bv.w;
        }
        __syncthreads();
    }
    #pragma unroll
    for (int u = 0; u < 2; u++) {
        const int m = m0 + ty * 2 + u;
        float4 v = make_float4(acc[u][0], acc[u][1], acc[u][2], acc[u][3]);
        *reinterpret_cast<float4*>(&g_Wx[m * OUTD + n0 + tx * 4]) = v;
    }
}

// ---------------------------------------------------------------------------
// E[i][h] = sum_f a[f] * Wx[i, h*64+f]
// ---------------------------------------------------------------------------
__global__ __launch_bounds__(128) void ecoef_kernel(const float* __restrict__ a) {
    const int i = blockIdx.x;
    const int h = threadIdx.x / 32;
    const int l = threadIdx.x % 32;
    const float* wrow = &g_Wx[i * OUTD + h * FH];
    float v = a[l] * wrow[l] + a[l + 32] * wrow[l + 32];
    #pragma unroll
    for (int off = 16; off > 0; off >>= 1)
        v += __shfl_xor_sync(0xffffffffu, v, off);
    if (l == 0) g_E[i * H + h] = v;
}

// ---------------------------------------------------------------------------
// Fused attention: per block = (8 i-rows, 1 head). 256 threads.
//   pass 1: e[ti][j] = 0.6*(Ei+Ej) + 0.4*sum_f a_f*|wi_f + wj_f|, adj-masked
//   pass 1b: row softmax (max, exp, sum) in smem
//   pass 2: out = softmax @ Wx
// ---------------------------------------------------------------------------
#define TI 8
#define TJ 32
__global__ __launch_bounds__(256) void attn_kernel(const int* __restrict__ adj,
                                                   const float* __restrict__ a,
                                                   float* __restrict__ out) {
    __shared__ float e_s[TI][N_NODES];   // 24 KB
    __shared__ float wxj[TJ][68];        // 8.5 KB (pad 68: float4 conflict-free)
    __shared__ float wxi[TI][FH];
    __shared__ float av[FH];
    __shared__ float ei_s[TI];
    __shared__ float ej_s[TJ];
    __shared__ float inv_s[TI];

    const int tid = threadIdx.x;
    const int h   = blockIdx.y;
    const int i0  = blockIdx.x * TI;
    const int warp = tid / 32;
    const int lane = tid % 32;

    // stage per-block constants (TI*FH = 512 > blockDim: must stride)
    for (int id = tid; id < TI * FH; id += 256) {
        const int ti = id / FH, f = id % FH;
        wxi[ti][f] = g_Wx[(i0 + ti) * OUTD + h * FH + f];
    }
    if (tid < FH) av[tid] = a[tid];
    if (tid < TI) ei_s[tid] = g_E[(i0 + tid) * H + h];
    __syncthreads();

    // -------- pass 1: raw attention scores --------
    for (int jt = 0; jt < N_NODES; jt += TJ) {
        #pragma unroll
        for (int r = 0; r < 2; r++) {               // TJ*FH = 512 float4s
            const int id = tid + r * 256;
            const int jj = id / 16, c4 = id % 16;
            float4 v = *reinterpret_cast<const float4*>(
                &g_Wx[(jt + jj) * OUTD + h * FH + c4 * 4]);
            *reinterpret_cast<float4*>(&wxj[jj][c4 * 4]) = v;
        }
        if (tid < TJ) ej_s[tid] = g_E[(jt + tid) * H + h];
        __syncthreads();
        {
            const int ti = warp;    // uniform per warp -> wxi reads broadcast
            const int jj = lane;
            const float4* wi4 = reinterpret_cast<const float4*>(&wxi[ti][0]);
            const float4* wj4 = reinterpret_cast<const float4*>(&wxj[jj][0]);
            const float4* a4p = reinterpret_cast<const float4*>(av);
            float acc = 0.f;
            #pragma unroll
            for (int f4 = 0; f4 < 16; f4++) {
                float4 si = wi4[f4];
                float4 sj = wj4[f4];
                float4 aa = a4p[f4];
                acc += aa.x * fabsf(si.x + sj.x);
                acc += aa.y * fabsf(si.y + sj.y);
                acc += aa.z * fabsf(si.z + sj.z);
                acc += aa.w * fabsf(si.w + sj.w);
            }
            float e = 0.6f * (ei_s[ti] + ej_s[jj]) + 0.4f * acc;
            if (adj[(i0 + ti) * N_NODES + jt + jj] == 0) e = -1e30f;
            e_s[ti][jt + jj] = e;
        }
        __syncthreads();
    }

    // -------- pass 1b: softmax per row (warp w owns row w) --------
    {
        const int ti = warp;
        float m = -1e30f;
        for (int j = lane; j < N_NODES; j += 32) m = fmaxf(m, e_s[ti][j]);
        #pragma unroll
        for (int off = 16; off > 0; off >>= 1)
            m = fmaxf(m, __shfl_xor_sync(0xffffffffu, m, off));
        float s = 0.f;
        for (int j = lane; j < N_NODES; j += 32) {
            float p = __expf(e_s[ti][j] - m);
            e_s[ti][j] = p;
            s += p;
        }
        #pragma unroll
        for (int off = 16; off > 0; off >>= 1)
            s += __shfl_xor_sync(0xffffffffu, s, off);
        if (lane == 0) inv_s[ti] = 1.f / s;
    }

    // -------- pass 2: out[ti][f] = inv * sum_j p[ti][j] * Wx[j][h*64+f] --------
    {
        const int f = tid % FH;
        const int g = tid / FH;    // 0..3 -> rows g and g+4
        float acc0 = 0.f, acc1 = 0.f;
        for (int jt = 0; jt < N_NODES; jt += TJ) {
            #pragma unroll
            for (int r = 0; r < 2; r++) {
                const int id = tid + r * 256;
                const int jj = id / 16, c4 = id % 16;
                float4 v = *reinterpret_cast<const float4*>(
                    &g_Wx[(jt + jj) * OUTD + h * FH + c4 * 4]);
                *reinterpret_cast<float4*>(&wxj[jj][c4 * 4]) = v;
            }
            __syncthreads();
            #pragma unroll
            for (int jj = 0; jj < TJ; jj++) {
                const float wv = wxj[jj][f];
                acc0 += e_s[g][jt + jj] * wv;
                acc1 += e_s[g + 4][jt + jj] * wv;
            }
            __syncthreads();
        }
        out[(i0 + g)     * OUTD + h * FH + f] = acc0 * inv_s[g];
        out[(i0 + g + 4) * OUTD + h * FH + f] = acc1 * inv_s[g + 4];
    }
}

// ---------------------------------------------------------------------------
extern "C" void kernel_launch(void* const* d_in, const int* in_sizes, int n_in,
                              void* d_out, int out_size) {
    // Identify inputs by element count (robust to metadata ordering):
    //   x:   768*256 = 196608 (f32)
    //   adj: 768*768 = 589824 (i32)
    //   W:   256*256 = 65536  (f32)
    //   a:   64             (f32)
    const float* x = nullptr;
    const int*   adj = nullptr;
    const float* W = nullptr;
    const float* a = nullptr;
    for (int i = 0; i < n_in; i++) {
        switch (in_sizes[i]) {
            case N_NODES * INP:      x   = (const float*)d_in[i]; break;
            case N_NODES * N_NODES:  adj = (const int*)d_in[i];   break;
            case OUTD * INP:         W   = (const float*)d_in[i]; break;
            case FH:                 a   = (const float*)d_in[i]; break;
            default: break;
        }
    }
    float* out = (float*)d_out;

    dim3 gg(OUTD / 64, N_NODES / 32);
    gemm_kernel<<<gg, 256>>>(x, W);
    ecoef_kernel<<<N_NODES, 128>>>(a);
    dim3 ga(N_NODES / TI, H);
    attn_kernel<<<ga, 256>>>(adj, a, out);
}

// round 3
// speedup vs baseline: 1.2039x; 1.2039x over previous
#include <cuda_runtime.h>

#define N_NODES 768
#define INP     256
#define H       4
#define FH      64
#define OUTD    256   // H*FH

typedef unsigned long long u64;

// Scratch (no cudaMalloc allowed)
__device__ float g_Wx[N_NODES * OUTD];
__device__ float g_E[N_NODES * H];

// ---------------- packed f32x2 helpers (sm_103a) ----------------
__device__ __forceinline__ u64 pk2(float x, float y) {
    u64 r; asm("mov.b64 %0,{%1,%2};" : "=l"(r) : "f"(x), "f"(y)); return r;
}
__device__ __forceinline__ float2 upk2(u64 v) {
    float2 r; asm("mov.b64 {%0,%1},%2;" : "=f"(r.x), "=f"(r.y) : "l"(v)); return r;
}
// acc += av * |wi + sj|   (elementwise on 2 packed fp32)
__device__ __forceinline__ void mac_abs2(u64& acc, u64 av, u64 wi, u64 sj) {
    u64 t;
    asm("add.rn.f32x2 %0,%1,%2;" : "=l"(t) : "l"(wi), "l"(sj));
    asm("and.b64 %0,%0,0x7FFFFFFF7FFFFFFF;" : "+l"(t));
    asm("fma.rn.f32x2 %0,%1,%2,%0;" : "+l"(acc) : "l"(av), "l"(t));
}
__device__ __forceinline__ void fma2(u64& acc, u64 a, u64 b) {
    asm("fma.rn.f32x2 %0,%1,%2,%0;" : "+l"(acc) : "l"(a), "l"(b));
}
__device__ __forceinline__ void mul2(u64& acc, u64 a) {
    asm("mul.rn.f32x2 %0,%0,%1;" : "+l"(acc) : "l"(a));
}

// ---------------------------------------------------------------------------
// GEMM: Wx = x @ W^T  (M=768, K=256, N=256), BM=32 BN=64 BK=32, 256 thr,
// register-prefetch double buffering. blockIdx.x == head (BN == FH).
// Fused epilogue computes E[i][h] = sum_f a[f]*Wx[i][h*64+f].
// ---------------------------------------------------------------------------
__global__ __launch_bounds__(256) void gemm_kernel(const float* __restrict__ x,
                                                   const float* __restrict__ W,
                                                   const float* __restrict__ a) {
    __shared__ float As[32][36];   // As[k][m]
    __shared__ float Bs[32][68];   // Bs[k][n]
    const int tid = threadIdx.x;
    const int m0 = blockIdx.y * 32;
    const int h  = blockIdx.x;           // BN=64 == FH -> block n-range is one head
    const int n0 = h * 64;

    const int xr = tid / 8;        // row within tile (0..31)
    const int xc = tid % 8;        // float4 column (0..7)
    const int tx = tid % 16;       // n quad
    const int ty = tid / 16;       // m pair
    float acc[2][4] = {};

    float4 px, pw0, pw1;
    {   // prefetch k0 = 0
        px  = *reinterpret_cast<const float4*>(&x[(m0 + xr) * INP + xc * 4]);
        pw0 = *reinterpret_cast<const float4*>(&W[(n0 + xr) * INP + xc * 4]);
        pw1 = *reinterpret_cast<const float4*>(&W[(n0 + xr + 32) * INP + xc * 4]);
    }

    #pragma unroll 1
    for (int it = 0; it < 8; it++) {
        __syncthreads();   // previous compute done before overwriting smem
        As[xc * 4 + 0][xr] = px.x;  As[xc * 4 + 1][xr] = px.y;
        As[xc * 4 + 2][xr] = px.z;  As[xc * 4 + 3][xr] = px.w;
        Bs[xc * 4 + 0][xr] = pw0.x; Bs[xc * 4 + 1][xr] = pw0.y;
        Bs[xc * 4 + 2][xr] = pw0.z; Bs[xc * 4 + 3][xr] = pw0.w;
        Bs[xc * 4 + 0][xr + 32] = pw1.x; Bs[xc * 4 + 1][xr + 32] = pw1.y;
        Bs[xc * 4 + 2][xr + 32] = pw1.z; Bs[xc * 4 + 3][xr + 32] = pw1.w;
        __syncthreads();
        if (it < 7) {   // prefetch next tile while computing
            const int k0 = (it + 1) * 32;
            px  = *reinterpret_cast<const float4*>(&x[(m0 + xr) * INP + k0 + xc * 4]);
            pw0 = *reinterpret_cast<const float4*>(&W[(n0 + xr) * INP + k0 + xc * 4]);
            pw1 = *reinterpret_cast<const float4*>(&W[(n0 + xr + 32) * INP + k0 + xc * 4]);
        }
        #pragma unroll
        for (int k = 0; k < 32; k++) {
            float2 av = *reinterpret_cast<const float2*>(&As[k][ty * 2]);
            float4 bv = *reinterpret_cast<const float4*>(&Bs[k][tx * 4]);
            acc[0][0] += av.x * bv.x; acc[0][1] += av.x * bv.y;
            acc[0][2] += av.x * bv.z; acc[0][3] += av.x * bv.w;
            acc[1][0] += av.y * bv.x; acc[1][1] += av.y * bv.y;
            acc[1][2] += av.y * bv.z; acc[1][3] += av.y * bv.w;
        }
    }

    // write Wx + fused E epilogue
    float4 a4v = *reinterpret_cast<const float4*>(&a[tx * 4]);   // f = tx*4+q
    #pragma unroll
    for (int u = 0; u < 2; u++) {
        const int m = m0 + ty * 2 + u;
        *reinterpret_cast<float4*>(&g_Wx[m * OUTD + n0 + tx * 4]) =
            make_float4(acc[u][0], acc[u][1], acc[u][2], acc[u][3]);
        float ev = a4v.x * acc[u][0] + a4v.y * acc[u][1]
                 + a4v.z * acc[u][2] + a4v.w * acc[u][3];
        #pragma unroll
        for (int off = 1; off < 16; off <<= 1)      // reduce over tx (half-warp)
            ev += __shfl_xor_sync(0xffffffffu, ev, off);
        if (tx == 0) g_E[m * H + h] = ev;
    }
}

// ---------------------------------------------------------------------------
// Fused flash-style attention. Block = (8 i-rows, head). Warp w owns row i0+w.
// Online softmax over j-tiles of 64; each wxj tile staged once and used for
// both e-computation and aggregation. Packed f32x2 math throughout.
//   e[i][j] = 0.6*(Ei+Ej) + 0.4*sum_f a_f*|wi_f+wj_f|   (lrelu identity)
// ---------------------------------------------------------------------------
#define TI 8
#define TJ 64
#define WXJ_PAD 70   // 70*4=280B: 8B-aligned rows, conflict-free LDS.64

__global__ __launch_bounds__(256) void attn_kernel(const int* __restrict__ adj,
                                                   const float* __restrict__ a,
                                                   float* __restrict__ out) {
    __shared__ float wxj[TJ][WXJ_PAD];        // 17.9 KB
    __shared__ float wxi[TI][FH];             // 2 KB
    __shared__ u64   av2[FH / 2];             // packed a pairs
    __shared__ u64   p_s[TI][TJ];             // 4 KB, packed (p,p)
    __shared__ float ej_s[N_NODES];           // 3 KB

    const int tid  = threadIdx.x;
    const int w    = tid / 32;
    const int lane = tid % 32;
    const int h    = blockIdx.y;
    const int i0   = blockIdx.x * TI;

    // stage per-block constants
    for (int id = tid; id < TI * FH; id += 256)
        wxi[id / FH][id % FH] = g_Wx[(i0 + id / FH) * OUTD + h * FH + id % FH];
    if (tid < FH / 2) av2[tid] = pk2(a[2 * tid], a[2 * tid + 1]);
    for (int id = tid; id < N_NODES; id += 256)
        ej_s[id] = g_E[id * H + h];
    // NOTE: first __syncthreads happens at top of the tile loop.

    const float Ei = g_E[(i0 + w) * H + h];   // warp-uniform
    float m = -1e30f, s = 0.f;
    u64 acc2 = 0;                             // out acc: f pair (2*lane, 2*lane+1)

    const int* adjrow = &adj[(i0 + w) * N_NODES];

    for (int jt = 0; jt < N_NODES; jt += TJ) {
        __syncthreads();   // (1st iter: constants visible; later: tile consumers done)
        // ---- stage wxj tile: 64 rows x 64 f ----
        #pragma unroll
        for (int r = 0; r < 4; r++) {
            const int id = tid + r * 256;          // 1024 float4s
            const int jj = id / 16, c4 = id % 16;
            float4 v = *reinterpret_cast<const float4*>(
                &g_Wx[(jt + jj) * OUTD + h * FH + c4 * 4]);
            // rows are 8B- (not 16B-) aligned: two 8B stores
            *reinterpret_cast<float2*>(&wxj[jj][c4 * 4])     = make_float2(v.x, v.y);
            *reinterpret_cast<float2*>(&wxj[jj][c4 * 4 + 2]) = make_float2(v.z, v.w);
        }
        __syncthreads();

        // ---- e for lane's two j columns ----
        const u64* wj0 = reinterpret_cast<const u64*>(&wxj[lane][0]);
        const u64* wj1 = reinterpret_cast<const u64*>(&wxj[lane + 32][0]);
        const u64* wi  = reinterpret_cast<const u64*>(&wxi[w][0]);
        u64 ea0 = 0, ea1 = 0;
        #pragma unroll
        for (int k = 0; k < FH / 2; k++) {
            const u64 wik = wi[k];
            const u64 avk = av2[k];
            mac_abs2(ea0, avk, wik, wj0[k]);
            mac_abs2(ea1, avk, wik, wj1[k]);
        }
        float2 f0 = upk2(ea0), f1 = upk2(ea1);
        float e0 = 0.6f * (Ei + ej_s[jt + lane])      + 0.4f * (f0.x + f0.y);
        float e1 = 0.6f * (Ei + ej_s[jt + 32 + lane]) + 0.4f * (f1.x + f1.y);
        if (adjrow[jt + lane]      == 0) e0 = -1e30f;
        if (adjrow[jt + 32 + lane] == 0) e1 = -1e30f;

        // ---- online softmax update (per warp/row) ----
        float tm = fmaxf(e0, e1);
        #pragma unroll
        for (int off = 16; off > 0; off >>= 1)
            tm = fmaxf(tm, __shfl_xor_sync(0xffffffffu, tm, off));
        const float mn = fmaxf(m, tm);
        const float sc = __expf(m - mn);
        const float p0 = __expf(e0 - mn);
        const float p1 = __expf(e1 - mn);
        s = s * sc + p0 + p1;
        mul2(acc2, pk2(sc, sc));
        m = mn;
        p_s[w][lane]      = pk2(p0, p0);
        p_s[w][lane + 32] = pk2(p1, p1);
        __syncwarp();

        // ---- aggregation: acc2 += sum_jj p[jj] * wxj[jj][2*lane..] ----
        const u64* pw = &p_s[w][0];
        #pragma unroll
        for (int jj = 0; jj < TJ; jj++) {
            const u64 p2 = pw[jj];                                        // bcast
            const u64 wv = *reinterpret_cast<const u64*>(&wxj[jj][lane * 2]);
            fma2(acc2, p2, wv);
        }
        // next tile's p_s overwrite is by the same warp (after its own agg) — safe;
        // wxj overwrite guarded by the loop-top __syncthreads.
    }

    // ---- epilogue: normalize and store ----
    #pragma unroll
    for (int off = 16; off > 0; off >>= 1)
        s += __shfl_xor_sync(0xffffffffu, s, off);
    const float inv = 1.f / s;
    float2 o = upk2(acc2);
    *reinterpret_cast<float2*>(&out[(i0 + w) * OUTD + h * FH + lane * 2]) =
        make_float2(o.x * inv, o.y * inv);
}

// ---------------------------------------------------------------------------
extern "C" void kernel_launch(void* const* d_in, const int* in_sizes, int n_in,
                              void* d_out, int out_size) {
    const float* x = nullptr;
    const int*   adj = nullptr;
    const float* W = nullptr;
    const float* a = nullptr;
    for (int i = 0; i < n_in; i++) {
        switch (in_sizes[i]) {
            case N_NODES * INP:      x   = (const float*)d_in[i]; break;
            case N_NODES * N_NODES:  adj = (const int*)d_in[i];   break;
            case OUTD * INP:         W   = (const float*)d_in[i]; break;
            case FH:                 a   = (const float*)d_in[i]; break;
            default: break;
        }
    }
    float* out = (float*)d_out;

    dim3 gg(H, N_NODES / 32);            // 4 x 24 = 96 blocks, bx == head
    gemm_kernel<<<gg, 256>>>(x, W, a);
    dim3 ga(N_NODES / TI, H);            // 96 x 4 = 384 blocks
    attn_kernel<<<ga, 256>>>(adj, a, out);
}

// round 4
// speedup vs baseline: 1.5623x; 1.2977x over previous
#include <cuda_runtime.h>

#define N_NODES 768
#define INP     256
#define H       4
#define FH      64
#define OUTD    256   // H*FH

typedef unsigned long long u64;

// Scratch (no cudaMalloc allowed)
__device__ float g_Wx[N_NODES * OUTD];
__device__ float g_E[N_NODES * H];

// ---------------- packed f32x2 helpers (sm_103a) ----------------
__device__ __forceinline__ u64 pk2(float x, float y) {
    u64 r; asm("mov.b64 %0,{%1,%2};" : "=l"(r) : "f"(x), "f"(y)); return r;
}
__device__ __forceinline__ float2 upk2(u64 v) {
    float2 r; asm("mov.b64 {%0,%1},%2;" : "=f"(r.x), "=f"(r.y) : "l"(v)); return r;
}
// acc += av * |wi + sj|   (elementwise on 2 packed fp32)
__device__ __forceinline__ void mac_abs2(u64& acc, u64 av, u64 wi, u64 sj) {
    u64 t;
    asm("add.rn.f32x2 %0,%1,%2;" : "=l"(t) : "l"(wi), "l"(sj));
    asm("and.b64 %0,%0,0x7FFFFFFF7FFFFFFF;" : "+l"(t));
    asm("fma.rn.f32x2 %0,%1,%2,%0;" : "+l"(acc) : "l"(av), "l"(t));
}
__device__ __forceinline__ void fma2(u64& acc, u64 a, u64 b) {
    asm("fma.rn.f32x2 %0,%1,%2,%0;" : "+l"(acc) : "l"(a), "l"(b));
}
__device__ __forceinline__ void mul2(u64& acc, u64 a) {
    asm("mul.rn.f32x2 %0,%0,%1;" : "+l"(acc) : "l"(a));
}

// ---------------------------------------------------------------------------
// GEMM: Wx = x @ W^T  (M=768, K=256, N=256), BM=32 BN=64 BK=32, 256 thr,
// register-prefetch double buffering. blockIdx.x == head (BN == FH).
// Fused epilogue computes E[i][h] = sum_f a[f]*Wx[i][h*64+f].
// ---------------------------------------------------------------------------
__global__ __launch_bounds__(256) void gemm_kernel(const float* __restrict__ x,
                                                   const float* __restrict__ W,
                                                   const float* __restrict__ a) {
    __shared__ float As[32][36];   // As[k][m]
    __shared__ float Bs[32][68];   // Bs[k][n]
    const int tid = threadIdx.x;
    const int m0 = blockIdx.y * 32;
    const int h  = blockIdx.x;           // BN=64 == FH -> block n-range is one head
    const int n0 = h * 64;

    const int xr = tid / 8;        // row within tile (0..31)
    const int xc = tid % 8;        // float4 column (0..7)
    const int tx = tid % 16;       // n quad
    const int ty = tid / 16;       // m pair
    float acc[2][4] = {};

    float4 px, pw0, pw1;
    {   // prefetch k0 = 0
        px  = *reinterpret_cast<const float4*>(&x[(m0 + xr) * INP + xc * 4]);
        pw0 = *reinterpret_cast<const float4*>(&W[(n0 + xr) * INP + xc * 4]);
        pw1 = *reinterpret_cast<const float4*>(&W[(n0 + xr + 32) * INP + xc * 4]);
    }

    #pragma unroll 1
    for (int it = 0; it < 8; it++) {
        __syncthreads();   // previous compute done before overwriting smem
        As[xc * 4 + 0][xr] = px.x;  As[xc * 4 + 1][xr] = px.y;
        As[xc * 4 + 2][xr] = px.z;  As[xc * 4 + 3][xr] = px.w;
        Bs[xc * 4 + 0][xr] = pw0.x; Bs[xc * 4 + 1][xr] = pw0.y;
        Bs[xc * 4 + 2][xr] = pw0.z; Bs[xc * 4 + 3][xr] = pw0.w;
        Bs[xc * 4 + 0][xr + 32] = pw1.x; Bs[xc * 4 + 1][xr + 32] = pw1.y;
        Bs[xc * 4 + 2][xr + 32] = pw1.z; Bs[xc * 4 + 3][xr + 32] = pw1.w;
        __syncthreads();
        if (it < 7) {   // prefetch next tile while computing
            const int k0 = (it + 1) * 32;
            px  = *reinterpret_cast<const float4*>(&x[(m0 + xr) * INP + k0 + xc * 4]);
            pw0 = *reinterpret_cast<const float4*>(&W[(n0 + xr) * INP + k0 + xc * 4]);
            pw1 = *reinterpret_cast<const float4*>(&W[(n0 + xr + 32) * INP + k0 + xc * 4]);
        }
        #pragma unroll
        for (int k = 0; k < 32; k++) {
            float2 av = *reinterpret_cast<const float2*>(&As[k][ty * 2]);
            float4 bv = *reinterpret_cast<const float4*>(&Bs[k][tx * 4]);
            acc[0][0] += av.x * bv.x; acc[0][1] += av.x * bv.y;
            acc[0][2] += av.x * bv.z; acc[0][3] += av.x * bv.w;
            acc[1][0] += av.y * bv.x; acc[1][1] += av.y * bv.y;
            acc[1][2] += av.y * bv.z; acc[1][3] += av.y * bv.w;
        }
    }

    // write Wx + fused E epilogue
    float4 a4v = *reinterpret_cast<const float4*>(&a[tx * 4]);   // f = tx*4+q
    #pragma unroll
    for (int u = 0; u < 2; u++) {
        const int m = m0 + ty * 2 + u;
        *reinterpret_cast<float4*>(&g_Wx[m * OUTD + n0 + tx * 4]) =
            make_float4(acc[u][0], acc[u][1], acc[u][2], acc[u][3]);
        float ev = a4v.x * acc[u][0] + a4v.y * acc[u][1]
                 + a4v.z * acc[u][2] + a4v.w * acc[u][3];
        #pragma unroll
        for (int off = 1; off < 16; off <<= 1)      // reduce over tx (half-warp)
            ev += __shfl_xor_sync(0xffffffffu, ev, off);
        if (tx == 0) g_E[m * H + h] = ev;
    }
}

// ---------------------------------------------------------------------------
// Fused flash-style attention. Block = (8 i-rows, head), 128 threads, 4 warps.
// Warp w owns rows (w, w+4): wj tile reads amortize over 2 rows.
// Online softmax over j-tiles of 64; p broadcast via shfl (no smem).
//   e[i][j] = 0.6*(Ei+Ej) + 0.4*sum_f a_f*|wi_f+wj_f|   (lrelu identity)
// ---------------------------------------------------------------------------
#define TI 8
#define TJ 64
#define WXJ_PAD 70   // 70 ≡ 6 mod 32; /2 = 35 ≡ 3 mod 32: conflict-free LDS.64 both ways

__global__ __launch_bounds__(128) void attn_kernel(const int* __restrict__ adj,
                                                   const float* __restrict__ a,
                                                   float* __restrict__ out) {
    __shared__ __align__(16) float wxj[TJ][WXJ_PAD];   // 17.9 KB
    __shared__ u64   wi2[TI][FH / 2];                  // packed wxi pairs, 2 KB
    __shared__ u64   av2[FH / 2];                      // packed a pairs
    __shared__ float e06[N_NODES];                     // 0.6*E_j, 3 KB

    const int tid  = threadIdx.x;
    const int w    = tid / 32;          // 0..3
    const int lane = tid % 32;
    const int h    = blockIdx.y;
    const int i0   = blockIdx.x * TI;

    // ---- stage per-block constants ----
    for (int id = tid; id < TI * FH / 2; id += 128) {
        const int r = id / (FH / 2), k = id % (FH / 2);
        wi2[r][k] = *reinterpret_cast<const u64*>(
            &g_Wx[(i0 + r) * OUTD + h * FH + 2 * k]);
    }
    if (tid < FH / 2)
        av2[tid] = *reinterpret_cast<const u64*>(&a[2 * tid]);
    for (int id = tid; id < N_NODES; id += 128)
        e06[id] = 0.6f * g_E[id * H + h];
    // first __syncthreads at top of tile loop orders these.

    const int ia = i0 + w, ib = i0 + w + 4;
    const float eia = 0.6f * g_E[ia * H + h];
    const float eib = 0.6f * g_E[ib * H + h];
    const int* adj_a = &adj[ia * N_NODES];
    const int* adj_b = &adj[ib * N_NODES];

    float m_a = -1e30f, s_a = 0.f, m_b = -1e30f, s_b = 0.f;
    u64 acc_a = 0, acc_b = 0;

    for (int jt = 0; jt < N_NODES; jt += TJ) {
        __syncthreads();   // prior tile fully consumed (and constants visible, iter 0)
        // ---- stage wxj tile: 64 rows x 64 f (1024 float4, 8 per thread) ----
        #pragma unroll
        for (int r = 0; r < 8; r++) {
            const int id = tid + r * 128;
            const int jj = id / 16, c4 = id % 16;
            float4 v = *reinterpret_cast<const float4*>(
                &g_Wx[(jt + jj) * OUTD + h * FH + c4 * 4]);
            *reinterpret_cast<float2*>(&wxj[jj][c4 * 4])     = make_float2(v.x, v.y);
            *reinterpret_cast<float2*>(&wxj[jj][c4 * 4 + 2]) = make_float2(v.z, v.w);
        }
        __syncthreads();

        // ---- e-phase: lane handles j = jt+lane and jt+32+lane, for both rows ----
        const u64* wj0 = reinterpret_cast<const u64*>(&wxj[lane][0]);
        const u64* wj1 = reinterpret_cast<const u64*>(&wxj[lane + 32][0]);
        u64 ea0 = 0, ea1 = 0, eb0 = 0, eb1 = 0;
        #pragma unroll
        for (int k = 0; k < FH / 2; k++) {
            const u64 avk = av2[k];
            const u64 wa  = wi2[w][k];
            const u64 wb  = wi2[w + 4][k];
            const u64 j0  = wj0[k];
            const u64 j1  = wj1[k];
            mac_abs2(ea0, avk, wa, j0);
            mac_abs2(ea1, avk, wa, j1);
            mac_abs2(eb0, avk, wb, j0);
            mac_abs2(eb1, avk, wb, j1);
        }
        float2 fa0 = upk2(ea0), fa1 = upk2(ea1), fb0 = upk2(eb0), fb1 = upk2(eb1);
        const float ej0 = e06[jt + lane], ej1 = e06[jt + 32 + lane];
        float e_a0 = eia + ej0 + 0.4f * (fa0.x + fa0.y);
        float e_a1 = eia + ej1 + 0.4f * (fa1.x + fa1.y);
        float e_b0 = eib + ej0 + 0.4f * (fb0.x + fb0.y);
        float e_b1 = eib + ej1 + 0.4f * (fb1.x + fb1.y);
        if (adj_a[jt + lane]      == 0) e_a0 = -1e30f;
        if (adj_a[jt + 32 + lane] == 0) e_a1 = -1e30f;
        if (adj_b[jt + lane]      == 0) e_b0 = -1e30f;
        if (adj_b[jt + 32 + lane] == 0) e_b1 = -1e30f;

        // ---- online softmax update (both rows) ----
        float tma = fmaxf(e_a0, e_a1);
        float tmb = fmaxf(e_b0, e_b1);
        #pragma unroll
        for (int off = 16; off > 0; off >>= 1) {
            tma = fmaxf(tma, __shfl_xor_sync(0xffffffffu, tma, off));
            tmb = fmaxf(tmb, __shfl_xor_sync(0xffffffffu, tmb, off));
        }
        const float mna = fmaxf(m_a, tma);
        const float mnb = fmaxf(m_b, tmb);
        const float sca = __expf(m_a - mna);
        const float scb = __expf(m_b - mnb);
        const float p_a0 = __expf(e_a0 - mna), p_a1 = __expf(e_a1 - mna);
        const float p_b0 = __expf(e_b0 - mnb), p_b1 = __expf(e_b1 - mnb);
        s_a = s_a * sca + p_a0 + p_a1;
        s_b = s_b * scb + p_b0 + p_b1;
        mul2(acc_a, pk2(sca, sca));
        mul2(acc_b, pk2(scb, scb));
        m_a = mna; m_b = mnb;

        // ---- aggregation: acc += p[jj] * wxj[jj][2*lane..] (p via shfl) ----
        #pragma unroll
        for (int jj = 0; jj < 32; jj++) {
            const u64 wv = *reinterpret_cast<const u64*>(&wxj[jj][lane * 2]);
            const float pa = __shfl_sync(0xffffffffu, p_a0, jj);
            const float pb = __shfl_sync(0xffffffffu, p_b0, jj);
            fma2(acc_a, pk2(pa, pa), wv);
            fma2(acc_b, pk2(pb, pb), wv);
        }
        #pragma unroll
        for (int jj = 0; jj < 32; jj++) {
            const u64 wv = *reinterpret_cast<const u64*>(&wxj[jj + 32][lane * 2]);
            const float pa = __shfl_sync(0xffffffffu, p_a1, jj);
            const float pb = __shfl_sync(0xffffffffu, p_b1, jj);
            fma2(acc_a, pk2(pa, pa), wv);
            fma2(acc_b, pk2(pb, pb), wv);
        }
    }

    // ---- epilogue: reduce s, normalize, store ----
    #pragma unroll
    for (int off = 16; off > 0; off >>= 1) {
        s_a += __shfl_xor_sync(0xffffffffu, s_a, off);
        s_b += __shfl_xor_sync(0xffffffffu, s_b, off);
    }
    const float inv_a = 1.f / s_a;
    const float inv_b = 1.f / s_b;
    float2 oa = upk2(acc_a), ob = upk2(acc_b);
    *reinterpret_cast<float2*>(&out[ia * OUTD + h * FH + lane * 2]) =
        make_float2(oa.x * inv_a, oa.y * inv_a);
    *reinterpret_cast<float2*>(&out[ib * OUTD + h * FH + lane * 2]) =
        make_float2(ob.x * inv_b, ob.y * inv_b);
}

// ---------------------------------------------------------------------------
extern "C" void kernel_launch(void* const* d_in, const int* in_sizes, int n_in,
                              void* d_out, int out_size) {
    const float* x = nullptr;
    const int*   adj = nullptr;
    const float* W = nullptr;
    const float* a = nullptr;
    for (int i = 0; i < n_in; i++) {
        switch (in_sizes[i]) {
            case N_NODES * INP:      x   = (const float*)d_in[i]; break;
            case N_NODES * N_NODES:  adj = (const int*)d_in[i];   break;
            case OUTD * INP:         W   = (const float*)d_in[i]; break;
            case FH:                 a   = (const float*)d_in[i]; break;
            default: break;
        }
    }
    float* out = (float*)d_out;

    dim3 gg(H, N_NODES / 32);            // 4 x 24 = 96 blocks, bx == head
    gemm_kernel<<<gg, 256>>>(x, W, a);
    dim3 ga(N_NODES / TI, H);            // 96 x 4 = 384 blocks
    attn_kernel<<<ga, 128>>>(adj, a, out);
}

// round 6
// speedup vs baseline: 1.9001x; 1.2162x over previous
#include <cuda_runtime.h>

#define N_NODES 768
#define INP     256
#define H       4
#define FH      64
#define OUTD    256   // H*FH
#define NSPLIT  4
#define JSPAN   (N_NODES / NSPLIT)   // 192
#define TI      16
#define TJ      64
#define WXJ_PAD 70

typedef unsigned long long u64;

// Scratch (no cudaMalloc allowed)
__device__ float g_Wx[N_NODES * OUTD];
__device__ float g_E[N_NODES * H];
__device__ float g_pm[N_NODES * H][NSPLIT];
__device__ float g_ps[N_NODES * H][NSPLIT];
__device__ float g_pacc[N_NODES * H][NSPLIT][FH];

// ---------------- packed f32x2 helpers (sm_103a) ----------------
__device__ __forceinline__ u64 pk2(float x, float y) {
    u64 r; asm("mov.b64 %0,{%1,%2};" : "=l"(r) : "f"(x), "f"(y)); return r;
}
__device__ __forceinline__ float2 upk2(u64 v) {
    float2 r; asm("mov.b64 {%0,%1},%2;" : "=f"(r.x), "=f"(r.y) : "l"(v)); return r;
}
__device__ __forceinline__ void mac_abs2(u64& acc, u64 av, u64 wi, u64 sj) {
    u64 t;
    asm("add.rn.f32x2 %0,%1,%2;" : "=l"(t) : "l"(wi), "l"(sj));
    asm("and.b64 %0,%0,0x7FFFFFFF7FFFFFFF;" : "+l"(t));
    asm("fma.rn.f32x2 %0,%1,%2,%0;" : "+l"(acc) : "l"(av), "l"(t));
}
__device__ __forceinline__ void fma2(u64& acc, u64 a, u64 b) {
    asm("fma.rn.f32x2 %0,%1,%2,%0;" : "+l"(acc) : "l"(a), "l"(b));
}
__device__ __forceinline__ void mul2(u64& acc, u64 a) {
    asm("mul.rn.f32x2 %0,%0,%1;" : "+l"(acc) : "l"(a));
}
// LDS.128 into two u64 (one broadcast feeds two packed operands)
__device__ __forceinline__ void lds_v2u64(u64& a, u64& b, const void* p) {
    unsigned s = (unsigned)__cvta_generic_to_shared(p);
    asm("ld.shared.v2.u64 {%0,%1}, [%2];" : "=l"(a), "=l"(b) : "r"(s));
}

// ---------------------------------------------------------------------------
// GEMM: Wx = x @ W^T, fused E epilogue
// ---------------------------------------------------------------------------
__global__ __launch_bounds__(256) void gemm_kernel(const float* __restrict__ x,
                                                   const float* __restrict__ W,
                                                   const float* __restrict__ a) {
    __shared__ float As[32][36];
    __shared__ float Bs[32][68];
    const int tid = threadIdx.x;
    const int m0 = blockIdx.y * 32;
    const int h  = blockIdx.x;
    const int n0 = h * 64;

    const int xr = tid / 8;
    const int xc = tid % 8;
    const int tx = tid % 16;
    const int ty = tid / 16;
    float acc[2][4] = {};

    float4 px, pw0, pw1;
    px  = *reinterpret_cast<const float4*>(&x[(m0 + xr) * INP + xc * 4]);
    pw0 = *reinterpret_cast<const float4*>(&W[(n0 + xr) * INP + xc * 4]);
    pw1 = *reinterpret_cast<const float4*>(&W[(n0 + xr + 32) * INP + xc * 4]);

    #pragma unroll 1
    for (int it = 0; it < 8; it++) {
        __syncthreads();
        As[xc * 4 + 0][xr] = px.x;  As[xc * 4 + 1][xr] = px.y;
        As[xc * 4 + 2][xr] = px.z;  As[xc * 4 + 3][xr] = px.w;
        Bs[xc * 4 + 0][xr] = pw0.x; Bs[xc * 4 + 1][xr] = pw0.y;
        Bs[xc * 4 + 2][xr] = pw0.z; Bs[xc * 4 + 3][xr] = pw0.w;
        Bs[xc * 4 + 0][xr + 32] = pw1.x; Bs[xc * 4 + 1][xr + 32] = pw1.y;
        Bs[xc * 4 + 2][xr + 32] = pw1.z; Bs[xc * 4 + 3][xr + 32] = pw1.w;
        __syncthreads();
        if (it < 7) {
            const int k0 = (it + 1) * 32;
            px  = *reinterpret_cast<const float4*>(&x[(m0 + xr) * INP + k0 + xc * 4]);
            pw0 = *reinterpret_cast<const float4*>(&W[(n0 + xr) * INP + k0 + xc * 4]);
            pw1 = *reinterpret_cast<const float4*>(&W[(n0 + xr + 32) * INP + k0 + xc * 4]);
        }
        #pragma unroll
        for (int k = 0; k < 32; k++) {
            float2 av = *reinterpret_cast<const float2*>(&As[k][ty * 2]);
            float4 bv = *reinterpret_cast<const float4*>(&Bs[k][tx * 4]);
            acc[0][0] += av.x * bv.x; acc[0][1] += av.x * bv.y;
            acc[0][2] += av.x * bv.z; acc[0][3] += av.x * bv.w;
            acc[1][0] += av.y * bv.x; acc[1][1] += av.y * bv.y;
            acc[1][2] += av.y * bv.z; acc[1][3] += av.y * bv.w;
        }
    }

    float4 a4v = *reinterpret_cast<const float4*>(&a[tx * 4]);
    #pragma unroll
    for (int u = 0; u < 2; u++) {
        const int m = m0 + ty * 2 + u;
        *reinterpret_cast<float4*>(&g_Wx[m * OUTD + n0 + tx * 4]) =
            make_float4(acc[u][0], acc[u][1], acc[u][2], acc[u][3]);
        float ev = a4v.x * acc[u][0] + a4v.y * acc[u][1]
                 + a4v.z * acc[u][2] + a4v.w * acc[u][3];
        #pragma unroll
        for (int off = 1; off < 16; off <<= 1)
            ev += __shfl_xor_sync(0xffffffffu, ev, off);
        if (tx == 0) g_E[m * H + h] = ev;
    }
}

// ---------------------------------------------------------------------------
// Split-KV flash attention. Block = (16 i-rows, head, j-split of 192).
// 128 threads, warp w owns rows {w, w+4, w+8, w+12}. Partial (m,s,acc) out.
// ---------------------------------------------------------------------------
__global__ __launch_bounds__(128) void attn_kernel(const int* __restrict__ adj,
                                                   const float* __restrict__ a) {
    __shared__ __align__(16) float wxj[TJ][WXJ_PAD];   // 17.9 KB
    __shared__ float4 wi4[2][4][32];                   // 4 KB: [q][warp][k] = 2 rows' f-pair
    __shared__ float4 p_ab[4][TJ];                     // 4 KB: (pa,pa,pb,pb)
    __shared__ float4 p_cd[4][TJ];                     // 4 KB
    __shared__ u64    av2[FH / 2];
    __shared__ float  e06s[JSPAN];                     // 0.6*E_j for this split

    const int tid  = threadIdx.x;
    const int w    = tid / 32;
    const int lane = tid % 32;
    const int h    = blockIdx.y;
    const int iblk = blockIdx.x >> 2;
    const int sp   = blockIdx.x & 3;
    const int i0   = iblk * TI;
    const int jbase = sp * JSPAN;

    // ---- stage per-block constants ----
    for (int id = tid; id < 256; id += 128) {          // wi4: 256 float4
        const int q = id >> 7, rem = id & 127;
        const int w2 = rem >> 5, k = rem & 31;
        const int r0 = w2 + 8 * q, r1 = r0 + 4;
        float2 lo = *reinterpret_cast<const float2*>(&g_Wx[(i0 + r0) * OUTD + h * FH + 2 * k]);
        float2 hi = *reinterpret_cast<const float2*>(&g_Wx[(i0 + r1) * OUTD + h * FH + 2 * k]);
        wi4[q][w2][k] = make_float4(lo.x, lo.y, hi.x, hi.y);
    }
    if (tid < FH / 2)
        av2[tid] = *reinterpret_cast<const u64*>(&a[2 * tid]);
    for (int id = tid; id < JSPAN; id += 128)
        e06s[id] = 0.6f * g_E[(jbase + id) * H + h];

    const int rA = i0 + w, rB = rA + 4, rC = rA + 8, rD = rA + 12;
    const float eiA = 0.6f * g_E[rA * H + h];
    const float eiB = 0.6f * g_E[rB * H + h];
    const float eiC = 0.6f * g_E[rC * H + h];
    const float eiD = 0.6f * g_E[rD * H + h];
    const int* adjA = &adj[rA * N_NODES + jbase];
    const int* adjB = &adj[rB * N_NODES + jbase];
    const int* adjC = &adj[rC * N_NODES + jbase];
    const int* adjD = &adj[rD * N_NODES + jbase];

    float mA = -1e30f, sA = 0.f, mB = -1e30f, sB = 0.f;
    float mC = -1e30f, sC = 0.f, mD = -1e30f, sD = 0.f;
    u64 accA = 0, accB = 0, accC = 0, accD = 0;

    for (int jt = 0; jt < JSPAN; jt += TJ) {
        __syncthreads();
        // ---- stage wxj tile (64 rows x 64 f): 1024 float4, 8/thread ----
        #pragma unroll
        for (int r = 0; r < 8; r++) {
            const int id = tid + r * 128;
            const int jj = id / 16, c4 = id % 16;
            float4 v = *reinterpret_cast<const float4*>(
                &g_Wx[(jbase + jt + jj) * OUTD + h * FH + c4 * 4]);
            *reinterpret_cast<float2*>(&wxj[jj][c4 * 4])     = make_float2(v.x, v.y);
            *reinterpret_cast<float2*>(&wxj[jj][c4 * 4 + 2]) = make_float2(v.z, v.w);
        }
        __syncthreads();

        // ---- e-phase: lane j-cols (jt+lane, jt+32+lane) x 4 rows ----
        const u64* wj0 = reinterpret_cast<const u64*>(&wxj[lane][0]);
        const u64* wj1 = reinterpret_cast<const u64*>(&wxj[lane + 32][0]);
        u64 eA0 = 0, eA1 = 0, eB0 = 0, eB1 = 0;
        u64 eC0 = 0, eC1 = 0, eD0 = 0, eD1 = 0;
        #pragma unroll
        for (int k = 0; k < 32; k++) {
            const u64 avk = av2[k];
            u64 wa, wb, wc, wd;
            lds_v2u64(wa, wb, &wi4[0][w][k]);
            lds_v2u64(wc, wd, &wi4[1][w][k]);
            const u64 j0 = wj0[k];
            const u64 j1 = wj1[k];
            mac_abs2(eA0, avk, wa, j0);  mac_abs2(eA1, avk, wa, j1);
            mac_abs2(eB0, avk, wb, j0);  mac_abs2(eB1, avk, wb, j1);
            mac_abs2(eC0, avk, wc, j0);  mac_abs2(eC1, avk, wc, j1);
            mac_abs2(eD0, avk, wd, j0);  mac_abs2(eD1, avk, wd, j1);
        }
        const float ej0 = e06s[jt + lane], ej1 = e06s[jt + 32 + lane];
        float2 f;
        f = upk2(eA0); float e_A0 = eiA + ej0 + 0.4f * (f.x + f.y);
        f = upk2(eA1); float e_A1 = eiA + ej1 + 0.4f * (f.x + f.y);
        f = upk2(eB0); float e_B0 = eiB + ej0 + 0.4f * (f.x + f.y);
        f = upk2(eB1); float e_B1 = eiB + ej1 + 0.4f * (f.x + f.y);
        f = upk2(eC0); float e_C0 = eiC + ej0 + 0.4f * (f.x + f.y);
        f = upk2(eC1); float e_C1 = eiC + ej1 + 0.4f * (f.x + f.y);
        f = upk2(eD0); float e_D0 = eiD + ej0 + 0.4f * (f.x + f.y);
        f = upk2(eD1); float e_D1 = eiD + ej1 + 0.4f * (f.x + f.y);
        if (adjA[jt + lane]      == 0) e_A0 = -1e30f;
        if (adjA[jt + 32 + lane] == 0) e_A1 = -1e30f;
        if (adjB[jt + lane]      == 0) e_B0 = -1e30f;
        if (adjB[jt + 32 + lane] == 0) e_B1 = -1e30f;
        if (adjC[jt + lane]      == 0) e_C0 = -1e30f;
        if (adjC[jt + 32 + lane] == 0) e_C1 = -1e30f;
        if (adjD[jt + lane]      == 0) e_D0 = -1e30f;
        if (adjD[jt + 32 + lane] == 0) e_D1 = -1e30f;

        // ---- online softmax update, 4 rows ----
        float tA = fmaxf(e_A0, e_A1), tB = fmaxf(e_B0, e_B1);
        float tC = fmaxf(e_C0, e_C1), tD = fmaxf(e_D0, e_D1);
        #pragma unroll
        for (int off = 16; off > 0; off >>= 1) {
            tA = fmaxf(tA, __shfl_xor_sync(0xffffffffu, tA, off));
            tB = fmaxf(tB, __shfl_xor_sync(0xffffffffu, tB, off));
            tC = fmaxf(tC, __shfl_xor_sync(0xffffffffu, tC, off));
            tD = fmaxf(tD, __shfl_xor_sync(0xffffffffu, tD, off));
        }
        const float nA = fmaxf(mA, tA), nB = fmaxf(mB, tB);
        const float nC = fmaxf(mC, tC), nD = fmaxf(mD, tD);
        const float scA = __expf(mA - nA), scB = __expf(mB - nB);
        const float scC = __expf(mC - nC), scD = __expf(mD - nD);
        const float pA0 = __expf(e_A0 - nA), pA1 = __expf(e_A1 - nA);
        const float pB0 = __expf(e_B0 - nB), pB1 = __expf(e_B1 - nB);
        const float pC0 = __expf(e_C0 - nC), pC1 = __expf(e_C1 - nC);
        const float pD0 = __expf(e_D0 - nD), pD1 = __expf(e_D1 - nD);
        sA = sA * scA + pA0 + pA1;  sB = sB * scB + pB0 + pB1;
        sC = sC * scC + pC0 + pC1;  sD = sD * scD + pD0 + pD1;
        mul2(accA, pk2(scA, scA));  mul2(accB, pk2(scB, scB));
        mul2(accC, pk2(scC, scC));  mul2(accD, pk2(scD, scD));
        mA = nA; mB = nB; mC = nC; mD = nD;

        p_ab[w][lane]      = make_float4(pA0, pA0, pB0, pB0);
        p_ab[w][lane + 32] = make_float4(pA1, pA1, pB1, pB1);
        p_cd[w][lane]      = make_float4(pC0, pC0, pD0, pD0);
        p_cd[w][lane + 32] = make_float4(pC1, pC1, pD1, pD1);
        __syncwarp();

        // ---- aggregation: one wv read feeds 4 rows ----
        #pragma unroll
        for (int jj = 0; jj < TJ; jj++) {
            const u64 wv = *reinterpret_cast<const u64*>(&wxj[jj][lane * 2]);
            u64 pa2, pb2, pc2, pd2;
            lds_v2u64(pa2, pb2, &p_ab[w][jj]);
            lds_v2u64(pc2, pd2, &p_cd[w][jj]);
            fma2(accA, pa2, wv);
            fma2(accB, pb2, wv);
            fma2(accC, pc2, wv);
            fma2(accD, pd2, wv);
        }
        __syncwarp();   // agg done before next tile's p overwrite
    }

    // ---- reduce per-lane s partials across the warp (BUG FIX vs round 5) ----
    #pragma unroll
    for (int off = 16; off > 0; off >>= 1) {
        sA += __shfl_xor_sync(0xffffffffu, sA, off);
        sB += __shfl_xor_sync(0xffffffffu, sB, off);
        sC += __shfl_xor_sync(0xffffffffu, sC, off);
        sD += __shfl_xor_sync(0xffffffffu, sD, off);
    }

    // ---- write partials (unnormalized) ----
    const int gA = rA * H + h, gB = rB * H + h, gC = rC * H + h, gD = rD * H + h;
    if (lane == 0) {
        g_pm[gA][sp] = mA; g_ps[gA][sp] = sA;
        g_pm[gB][sp] = mB; g_ps[gB][sp] = sB;
        g_pm[gC][sp] = mC; g_ps[gC][sp] = sC;
        g_pm[gD][sp] = mD; g_ps[gD][sp] = sD;
    }
    float2 o;
    o = upk2(accA); *reinterpret_cast<float2*>(&g_pacc[gA][sp][2 * lane]) = o;
    o = upk2(accB); *reinterpret_cast<float2*>(&g_pacc[gB][sp][2 * lane]) = o;
    o = upk2(accC); *reinterpret_cast<float2*>(&g_pacc[gC][sp][2 * lane]) = o;
    o = upk2(accD); *reinterpret_cast<float2*>(&g_pacc[gD][sp][2 * lane]) = o;
}

// ---------------------------------------------------------------------------
// Combine: merge NSPLIT partial softmaxes per (i,h) row. Warp per row.
// ---------------------------------------------------------------------------
__global__ __launch_bounds__(256) void combine_kernel(float* __restrict__ out) {
    const int tid  = threadIdx.x;
    const int w    = tid / 32;
    const int lane = tid % 32;
    const int r    = blockIdx.x * 8 + w;     // 0..3071
    const int i    = r / H;
    const int h    = r % H;

    float mp = (lane < NSPLIT) ? g_pm[r][lane] : -1e30f;
    float ms = mp;
    #pragma unroll
    for (int off = 16; off > 0; off >>= 1)
        ms = fmaxf(ms, __shfl_xor_sync(0xffffffffu, ms, off));
    float fac = (lane < NSPLIT) ? __expf(mp - ms) : 0.f;
    float sv  = (lane < NSPLIT) ? g_ps[r][lane] * fac : 0.f;
    #pragma unroll
    for (int off = 16; off > 0; off >>= 1)
        sv += __shfl_xor_sync(0xffffffffu, sv, off);
    const float f0 = __shfl_sync(0xffffffffu, fac, 0);
    const float f1 = __shfl_sync(0xffffffffu, fac, 1);
    const float f2 = __shfl_sync(0xffffffffu, fac, 2);
    const float f3 = __shfl_sync(0xffffffffu, fac, 3);

    float2 a0 = *reinterpret_cast<const float2*>(&g_pacc[r][0][2 * lane]);
    float2 a1 = *reinterpret_cast<const float2*>(&g_pacc[r][1][2 * lane]);
    float2 a2 = *reinterpret_cast<const float2*>(&g_pacc[r][2][2 * lane]);
    float2 a3 = *reinterpret_cast<const float2*>(&g_pacc[r][3][2 * lane]);
    const float inv = 1.f / sv;
    float ox = (a0.x * f0 + a1.x * f1 + a2.x * f2 + a3.x * f3) * inv;
    float oy = (a0.y * f0 + a1.y * f1 + a2.y * f2 + a3.y * f3) * inv;
    *reinterpret_cast<float2*>(&out[i * OUTD + h * FH + 2 * lane]) = make_float2(ox, oy);
}

// ---------------------------------------------------------------------------
extern "C" void kernel_launch(void* const* d_in, const int* in_sizes, int n_in,
                              void* d_out, int out_size) {
    const float* x = nullptr;
    const int*   adj = nullptr;
    const float* W = nullptr;
    const float* a = nullptr;
    for (int i = 0; i < n_in; i++) {
        switch (in_sizes[i]) {
            case N_NODES * INP:      x   = (const float*)d_in[i]; break;
            case N_NODES * N_NODES:  adj = (const int*)d_in[i];   break;
            case OUTD * INP:         W   = (const float*)d_in[i]; break;
            case FH:                 a   = (const float*)d_in[i]; break;
            default: break;
        }
    }
    float* out = (float*)d_out;

    dim3 gg(H, N_NODES / 32);                     // 96 blocks
    gemm_kernel<<<gg, 256>>>(x, W, a);
    dim3 ga((N_NODES / TI) * NSPLIT, H);          // 192 x 4 = 768 blocks
    attn_kernel<<<ga, 128>>>(adj, a);
    combine_kernel<<<N_NODES * H / 8, 256>>>(out);   // 384 blocks
}